// round 9
// baseline (speedup 1.0000x reference)
#include <cuda_runtime.h>
#include <cstdint>

// Problem constants (fixed by the reference): D=64, K=1024, N=65536.
#define DIM   64
#define MBLK  128          // rows per CTA
#define NBLK  128          // codes per smem tile
#define TM    8            // rows per thread
#define MAXK  4096

__device__ float g_c2[MAXK];   // ||w_k||^2, sequential fp32 sum

// Packed fp32x2 fused multiply-add (FFMA2). Each half is an IEEE fp32 FMA,
// so per-output accumulation chains are bit-identical to scalar fmaf chains.
__device__ __forceinline__ unsigned long long ffma2(unsigned long long a,
                                                    unsigned long long b,
                                                    unsigned long long c) {
    unsigned long long d;
    asm("fma.rn.f32x2 %0, %1, %2, %3;" : "=l"(d) : "l"(a), "l"(b), "l"(c));
    return d;
}

// ---------------------------------------------------------------------------
// C2[k] = sum_d W[k][d]^2, sequential (mul then add, round-to-nearest each op)
// ---------------------------------------------------------------------------
__global__ void c2_kernel(const float* __restrict__ W, int K) {
    int k = blockIdx.x * blockDim.x + threadIdx.x;
    if (k >= K) return;
    const float* w = W + k * DIM;
    float s = 0.0f;
#pragma unroll
    for (int d = 0; d < DIM; ++d)
        s = __fadd_rn(s, __fmul_rn(w[d], w[d]));
    g_c2[k] = s;
}

// ---------------------------------------------------------------------------
// Main VQ kernel: per-CTA 128 rows vs all K codes.
// acc[(row, code-pair)] += (w_c0, w_c1) * (x, x)  via FFMA2.
// X tile stored DUPLICATED (x,x); W tile stored natural (code-major pairs).
// dist = ((L2 - 2*dot) + C2) in fp32, argmin with first-index tie-break.
// ---------------------------------------------------------------------------
__global__ void __launch_bounds__(256, 2)
vq_kernel(const float* __restrict__ X, const float* __restrict__ W,
          float* __restrict__ outQ, float* __restrict__ outI, int K)
{
    extern __shared__ float smem[];
    float* xs2 = smem;                               // [DIM][2*MBLK] dup  16384 f
    float* ws  = smem + DIM * 2 * MBLK;              // [DIM][NBLK]         8192 f
    float* l2s = smem + DIM * 2 * MBLK + DIM * NBLK; // [MBLK]               128 f

    const int tid = threadIdx.x;
    const int tx  = tid & 15;        // code group (owns codes 4tx..4tx+3, 64+4tx..)
    const int ty  = tid >> 4;        // row group (8 rows)
    const int rowbase = blockIdx.x * MBLK;

    // ---- load X tile, transposed + duplicated: xs2[d][2m]=xs2[d][2m+1]=X[m][d]
    {
        int r = tid >> 1, h = tid & 1;
        const float4* src = (const float4*)(X + (size_t)(rowbase + r) * DIM + h * 32);
        float2* xrow = (float2*)xs2 + r;             // float2 idx, row stride MBLK
#pragma unroll
        for (int q = 0; q < 8; ++q) {
            float4 v = src[q];
            int d = h * 32 + q * 4;
            xrow[(size_t)(d + 0) * MBLK] = make_float2(v.x, v.x);
            xrow[(size_t)(d + 1) * MBLK] = make_float2(v.y, v.y);
            xrow[(size_t)(d + 2) * MBLK] = make_float2(v.z, v.z);
            xrow[(size_t)(d + 3) * MBLK] = make_float2(v.w, v.w);
        }
    }
    __syncthreads();

    // ---- L2 per row: sequential fp32 (mul, then add) ----
    if (tid < MBLK) {
        float s = 0.0f;
#pragma unroll
        for (int d = 0; d < DIM; ++d) {
            float v = xs2[d * 2 * MBLK + 2 * tid];
            s = __fadd_rn(s, __fmul_rn(v, v));
        }
        l2s[tid] = s;
    }
    __syncthreads();

    float l2r[TM];
#pragma unroll
    for (int r = 0; r < TM; ++r) l2r[r] = l2s[ty * TM + r];

    float bestd[TM];
    int   besti[TM];
#pragma unroll
    for (int r = 0; r < TM; ++r) { bestd[r] = 3.4e38f; besti[r] = 0; }

    const int ntiles = K / NBLK;
    for (int t = 0; t < ntiles; ++t) {
        const int cb = t * NBLK;

        // ---- load W tile, natural transposed layout: ws[d][c] = W[cb+c][d]
        {
            int c = tid >> 1, h = tid & 1;
            const float4* src = (const float4*)(W + (size_t)(cb + c) * DIM + h * 32);
#pragma unroll
            for (int q = 0; q < 8; ++q) {
                float4 v = src[q];
                int d = h * 32 + q * 4;
                ws[(d + 0) * NBLK + c] = v.x;
                ws[(d + 1) * NBLK + c] = v.y;
                ws[(d + 2) * NBLK + c] = v.z;
                ws[(d + 3) * NBLK + c] = v.w;
            }
        }
        __syncthreads();

        // ---- mainloop: 8 rows x 4 code-pairs per thread.
        // W: LDS.128 at 16B*tx -> contiguous 256B, conflict-free (2 wf, dedup halves).
        // X: LDS.128 of (x,x) pairs, 16 lanes same addr -> broadcast (1 wf).
        unsigned long long acc[TM][4];
#pragma unroll
        for (int r = 0; r < TM; ++r)
#pragma unroll
            for (int p = 0; p < 4; ++p) acc[r][p] = 0ull;   // (0.f, 0.f)

        const float* pxf = xs2 + ty * (2 * TM);   // float2 idx ty*8 (rows 8ty..)
        const float* pwf = ws + tx * 4;           // codes 4tx..4tx+3
#pragma unroll 4
        for (int d = 0; d < DIM; ++d) {
            ulonglong2 x0 = *(const ulonglong2*)(pxf);        // rows 8ty+0,1
            ulonglong2 x1 = *(const ulonglong2*)(pxf + 4);    // rows 8ty+2,3
            ulonglong2 x2 = *(const ulonglong2*)(pxf + 8);    // rows 8ty+4,5
            ulonglong2 x3 = *(const ulonglong2*)(pxf + 12);   // rows 8ty+6,7
            ulonglong2 w0 = *(const ulonglong2*)(pwf);        // codes 4tx..4tx+3
            ulonglong2 w1 = *(const ulonglong2*)(pwf + 64);   // codes 64+4tx..+3
            pxf += 2 * MBLK; pwf += NBLK;
            unsigned long long xv[8] = {x0.x, x0.y, x1.x, x1.y, x2.x, x2.y, x3.x, x3.y};
            unsigned long long wv[4] = {w0.x, w0.y, w1.x, w1.y};
#pragma unroll
            for (int r = 0; r < TM; ++r)
#pragma unroll
                for (int p = 0; p < 4; ++p)
                    acc[r][p] = ffma2(wv[p], xv[r], acc[r][p]);
        }

        // ---- per-tile epilogue: distances + running argmin (codes ascending)
#pragma unroll
        for (int p = 0; p < 4; ++p) {
            int code0 = cb + 64 * (p >> 1) + 4 * tx + 2 * (p & 1);  // even code of pair
            float c2a = __ldg(&g_c2[code0]);
            float c2b = __ldg(&g_c2[code0 + 1]);
#pragma unroll
            for (int r = 0; r < TM; ++r) {
                float lo = __uint_as_float((unsigned)(acc[r][p] & 0xffffffffull));
                float hi = __uint_as_float((unsigned)(acc[r][p] >> 32));
                float el = l2r[r];
                float d0 = __fadd_rn(__fsub_rn(el, __fmul_rn(2.0f, lo)), c2a);
                float d1 = __fadd_rn(__fsub_rn(el, __fmul_rn(2.0f, hi)), c2b);
                if (d0 < bestd[r]) { bestd[r] = d0; besti[r] = code0; }
                if (d1 < bestd[r]) { bestd[r] = d1; besti[r] = code0 + 1; }
            }
        }
        __syncthreads();   // ws reuse next tile
    }

    // ---- cross-thread reduction over the 16 code groups (tx), padded stride 17.
    // Tie-break on smallest index handles interleaved code ownership.
    float* redD = xs2;                         // 128*17 floats
    int*   redI = (int*)(xs2 + 128 * 17);      // 128*17 ints
    int*   bidx = (int*)(xs2 + 2 * 128 * 17);  // 128 ints
#pragma unroll
    for (int r = 0; r < TM; ++r) {
        int row = ty * TM + r;
        redD[row * 17 + tx] = bestd[r];
        redI[row * 17 + tx] = besti[r];
    }
    __syncthreads();

    if (tid < MBLK) {
        float bd = redD[tid * 17];
        int   bi = redI[tid * 17];
#pragma unroll
        for (int u = 1; u < 16; ++u) {
            float dv = redD[tid * 17 + u];
            int   iv = redI[tid * 17 + u];
            if (dv < bd || (dv == bd && iv < bi)) { bd = dv; bi = iv; }
        }
        bidx[tid] = bi;
        if (outI) outI[rowbase + tid] = (float)bi;
    }
    __syncthreads();

    // ---- gather quantized = W[closest]
    if (outQ) {
        int r = tid >> 1, h = tid & 1;
        int idx = bidx[r];
        const float4* src = (const float4*)(W + (size_t)idx * DIM + h * 32);
        float4* dst = (float4*)(outQ + (size_t)(rowbase + r) * DIM + h * 32);
#pragma unroll
        for (int q = 0; q < 8; ++q) dst[q] = __ldg(src + q);
    }
}

// ---------------------------------------------------------------------------
extern "C" void kernel_launch(void* const* d_in, const int* in_sizes, int n_in,
                              void* d_out, int out_size) {
    const float* X = (const float*)d_in[0];
    const float* W = (const float*)d_in[1];
    int N = in_sizes[0] / DIM;
    int K = in_sizes[1] / DIM;

    long long nd = (long long)N * DIM;
    float* outQ = nullptr;
    float* outI = nullptr;
    if ((long long)out_size >= nd + N) { outQ = (float*)d_out; outI = (float*)d_out + nd; }
    else if ((long long)out_size == nd) { outQ = (float*)d_out; }
    else { outI = (float*)d_out; }

    size_t smembytes = (size_t)(DIM * 2 * MBLK + DIM * NBLK + MBLK) * sizeof(float);
    cudaFuncSetAttribute(vq_kernel, cudaFuncAttributeMaxDynamicSharedMemorySize,
                         (int)smembytes);

    c2_kernel<<<(K + 255) / 256, 256>>>(W, K);
    vq_kernel<<<N / MBLK, 256, smembytes>>>(X, W, outQ, outI, K);
}

// round 10
// speedup vs baseline: 1.2040x; 1.2040x over previous
#include <cuda_runtime.h>
#include <cstdint>

// Problem constants (fixed by the reference): D=64, K=1024, N=65536.
#define DIM   64
#define MBLK  256          // rows per CTA
#define NBLK  128          // codes per smem tile
#define TM    16           // rows per thread (8 packed pairs)
#define MAXK  4096

__device__ float g_c2[MAXK];   // ||w_k||^2, sequential fp32 sum

// Packed fp32x2 fused multiply-add (FFMA2). Each half is an IEEE fp32 FMA,
// so per-output accumulation chains are bit-identical to scalar fmaf chains.
__device__ __forceinline__ unsigned long long ffma2(unsigned long long a,
                                                    unsigned long long b,
                                                    unsigned long long c) {
    unsigned long long d;
    asm("fma.rn.f32x2 %0, %1, %2, %3;" : "=l"(d) : "l"(a), "l"(b), "l"(c));
    return d;
}

__device__ __forceinline__ void unpack2(unsigned long long v, float& lo, float& hi) {
    asm("mov.b64 {%0, %1}, %2;" : "=f"(lo), "=f"(hi) : "l"(v));
}

// ---------------------------------------------------------------------------
// C2[k] = sum_d W[k][d]^2, sequential (mul then add, round-to-nearest each op)
// ---------------------------------------------------------------------------
__global__ void c2_kernel(const float* __restrict__ W, int K) {
    int k = blockIdx.x * blockDim.x + threadIdx.x;
    if (k >= K) return;
    const float* w = W + k * DIM;
    float s = 0.0f;
#pragma unroll
    for (int d = 0; d < DIM; ++d)
        s = __fadd_rn(s, __fmul_rn(w[d], w[d]));
    g_c2[k] = s;
}

// ---------------------------------------------------------------------------
// Main VQ kernel: per-CTA 256 rows vs all K codes.
// acc[(row-pair, code)] += (x_r0, x_r1) * (w, w)   via FFMA2.
// X natural transposed; W transposed + duplicated.
// dist = ((L2 - 2*dot) + C2) in fp32, argmin with first-index tie-break.
// ---------------------------------------------------------------------------
__global__ void __launch_bounds__(256, 1)
vq_kernel(const float* __restrict__ X, const float* __restrict__ W,
          float* __restrict__ outQ, float* __restrict__ outI, int K)
{
    extern __shared__ float smem[];
    float* xs  = smem;                               // [DIM][MBLK]     16384 f
    float* ws  = smem + DIM * MBLK;                  // [DIM][2*NBLK]   16384 f (dup)
    float* l2s = smem + DIM * MBLK + DIM * 2 * NBLK; // [MBLK]            256 f

    const int tid = threadIdx.x;
    const int tx  = tid & 15;        // code group
    const int ty  = tid >> 4;        // row group (16 rows each)
    const int rowbase = blockIdx.x * MBLK;

    // ---- load X tile, transposed into xs[d][m]: one full row per thread ----
    {
        const float4* src = (const float4*)(X + (size_t)(rowbase + tid) * DIM);
#pragma unroll
        for (int q = 0; q < 16; ++q) {
            float4 v = src[q];
            int d = q * 4;
            xs[(d + 0) * MBLK + tid] = v.x;
            xs[(d + 1) * MBLK + tid] = v.y;
            xs[(d + 2) * MBLK + tid] = v.z;
            xs[(d + 3) * MBLK + tid] = v.w;
        }
    }
    __syncthreads();

    // ---- L2 per row: sequential fp32 (mul, then add) ----
    {
        float s = 0.0f;
#pragma unroll
        for (int d = 0; d < DIM; ++d) {
            float v = xs[d * MBLK + tid];
            s = __fadd_rn(s, __fmul_rn(v, v));
        }
        l2s[tid] = s;
    }
    __syncthreads();

    float bestd[TM];
    int   besti[TM];
#pragma unroll
    for (int r = 0; r < TM; ++r) { bestd[r] = 3.4e38f; besti[r] = 0; }

    const int ntiles = K / NBLK;
    for (int t = 0; t < ntiles; ++t) {
        const int cb = t * NBLK;

        // ---- load W tile, transposed + duplicated: ws[d][2c]=ws[d][2c+1]=W[cb+c][d]
        {
            int c = tid >> 1, h = tid & 1;
            const float4* src = (const float4*)(W + (size_t)(cb + c) * DIM + h * 32);
            float2* wrow = (float2*)ws + c;          // column c (float2 idx), row stride NBLK f2
#pragma unroll
            for (int q = 0; q < 8; ++q) {
                float4 v = src[q];
                int d = h * 32 + q * 4;
                wrow[(size_t)(d + 0) * NBLK] = make_float2(v.x, v.x);
                wrow[(size_t)(d + 1) * NBLK] = make_float2(v.y, v.y);
                wrow[(size_t)(d + 2) * NBLK] = make_float2(v.z, v.z);
                wrow[(size_t)(d + 3) * NBLK] = make_float2(v.w, v.w);
            }
        }
        __syncthreads();

        // ---- mainloop: 16 rows (8 pairs) x 8 codes per thread, FFMA2.
        // W: thread tx owns codes {32q + 2tx, 32q + 2tx + 1 : q=0..3}; each W LDS.128
        // reads bytes 16*tx + 256*q -> contiguous 256B across half-warp, conflict-free.
        // X: 4 LDS.128, both half-warps broadcast.
        // Inner 8 d-steps fully unrolled with immediate offsets; pointer update 1x per 8.
        unsigned long long acc[8][8];
#pragma unroll
        for (int p = 0; p < 8; ++p)
#pragma unroll
            for (int j = 0; j < 8; ++j) acc[p][j] = 0ull;   // (0.f, 0.f)

        const float* px = xs + ty * TM;
        const float* pw = ws + tx * 4;
#pragma unroll 1
        for (int db = 0; db < DIM; db += 8) {
#pragma unroll
            for (int dd = 0; dd < 8; ++dd) {
                const float* cpx = px + dd * MBLK;
                const float* cpw = pw + dd * (2 * NBLK);
                ulonglong2 xa = *(const ulonglong2*)(cpx);
                ulonglong2 xb = *(const ulonglong2*)(cpx + 4);
                ulonglong2 xc = *(const ulonglong2*)(cpx + 8);
                ulonglong2 xd = *(const ulonglong2*)(cpx + 12);
                ulonglong2 w0 = *(const ulonglong2*)(cpw);        // codes 2tx, 2tx+1
                ulonglong2 w1 = *(const ulonglong2*)(cpw + 64);   // codes 32+2tx, 33+2tx
                ulonglong2 w2 = *(const ulonglong2*)(cpw + 128);  // codes 64+..
                ulonglong2 w3 = *(const ulonglong2*)(cpw + 192);  // codes 96+..
                unsigned long long xv[8] = {xa.x, xa.y, xb.x, xb.y, xc.x, xc.y, xd.x, xd.y};
                unsigned long long wv[8] = {w0.x, w0.y, w1.x, w1.y, w2.x, w2.y, w3.x, w3.y};
#pragma unroll
                for (int p = 0; p < 8; ++p)
#pragma unroll
                    for (int j = 0; j < 8; ++j)
                        acc[p][j] = ffma2(xv[p], wv[j], acc[p][j]);
            }
            px += 8 * MBLK;
            pw += 8 * (2 * NBLK);
        }

        // ---- per-tile epilogue: distances + running argmin (codes ascending per thread)
#pragma unroll
        for (int j = 0; j < 8; ++j) {
            int code = cb + 32 * (j >> 1) + 2 * tx + (j & 1);
            float c2 = __ldg(&g_c2[code]);
#pragma unroll
            for (int p = 0; p < 8; ++p) {
                float lo, hi;
                unpack2(acc[p][j], lo, hi);
                int r0 = 2 * p, r1 = 2 * p + 1;
                float el0 = l2s[ty * TM + r0];
                float el1 = l2s[ty * TM + r1];
                float d0 = __fadd_rn(__fsub_rn(el0, __fmul_rn(2.0f, lo)), c2);
                float d1 = __fadd_rn(__fsub_rn(el1, __fmul_rn(2.0f, hi)), c2);
                if (d0 < bestd[r0]) { bestd[r0] = d0; besti[r0] = code; }
                if (d1 < bestd[r1]) { bestd[r1] = d1; besti[r1] = code; }
            }
        }
        __syncthreads();   // ws reuse next tile
    }

    // ---- cross-thread reduction over the 16 code groups (tx), padded stride 17.
    // Tie-break on smallest index handles the interleaved code ownership.
    float* redD = ws;                         // 256*17 floats
    int*   redI = (int*)(ws + 256 * 17);      // 256*17 ints
    int*   bidx = (int*)(ws + 2 * 256 * 17);  // 256 ints
#pragma unroll
    for (int r = 0; r < TM; ++r) {
        int row = ty * TM + r;
        redD[row * 17 + tx] = bestd[r];
        redI[row * 17 + tx] = besti[r];
    }
    __syncthreads();

    {
        float bd = redD[tid * 17];
        int   bi = redI[tid * 17];
#pragma unroll
        for (int u = 1; u < 16; ++u) {
            float dv = redD[tid * 17 + u];
            int   iv = redI[tid * 17 + u];
            if (dv < bd || (dv == bd && iv < bi)) { bd = dv; bi = iv; }
        }
        bidx[tid] = bi;
        if (outI) outI[rowbase + tid] = (float)bi;
    }
    __syncthreads();

    // ---- gather quantized = W[closest]: one row per thread
    if (outQ) {
        int idx = bidx[tid];
        const float4* src = (const float4*)(W + (size_t)idx * DIM);
        float4* dst = (float4*)(outQ + (size_t)(rowbase + tid) * DIM);
#pragma unroll
        for (int q = 0; q < 16; ++q) dst[q] = __ldg(src + q);
    }
}

// ---------------------------------------------------------------------------
extern "C" void kernel_launch(void* const* d_in, const int* in_sizes, int n_in,
                              void* d_out, int out_size) {
    const float* X = (const float*)d_in[0];
    const float* W = (const float*)d_in[1];
    int N = in_sizes[0] / DIM;
    int K = in_sizes[1] / DIM;

    long long nd = (long long)N * DIM;
    float* outQ = nullptr;
    float* outI = nullptr;
    if ((long long)out_size >= nd + N) { outQ = (float*)d_out; outI = (float*)d_out + nd; }
    else if ((long long)out_size == nd) { outQ = (float*)d_out; }
    else { outI = (float*)d_out; }

    size_t smembytes = (size_t)(DIM * MBLK + DIM * 2 * NBLK + MBLK) * sizeof(float);
    cudaFuncSetAttribute(vq_kernel, cudaFuncAttributeMaxDynamicSharedMemorySize,
                         (int)smembytes);

    c2_kernel<<<(K + 255) / 256, 256>>>(W, K);
    vq_kernel<<<N / MBLK, 256, smembytes>>>(X, W, outQ, outI, K);
}